// round 4
// baseline (speedup 1.0000x reference)
#include <cuda_runtime.h>
#include <cuda_fp16.h>
#include <cstdint>

#define NN 100000
#define EE 1600000
#define DD 64
#define NB 98            // ceil(NN/1024)
#define GEMM_BLOCKS 782  // ceil(NN/128)
#define DEG_BLOCKS 6250  // EE/256

// ---------------- device scratch ----------------
__device__ int    g_degi[NN];
__device__ int    g_start[NN];
__device__ float  g_dinv[NN];
__device__ float  g_invdeg[NN];
__device__ int    g_rank[EE];      // edge's rank within its target bucket
__device__ int    g_csr[EE];       // source node per CSR slot
__device__ uint2  g_yh[NN * 16];   // y = x @ W^T in fp16: 4 halfs per uint2
__device__ unsigned long long g_state[NB];
__device__ int    g_ticket;

// ---------------------------------------------------------------------------
__global__ void clear_kernel() {
    int i = blockIdx.x * blockDim.x + threadIdx.x;
    if (i < NN) g_degi[i] = 0;
    if (i < NB) g_state[i] = 0ULL;
    if (i == 0) g_ticket = 0;
}

// ---------------------------------------------------------------------------
__device__ __forceinline__ unsigned f2tf32(float f) {
    unsigned u;
    asm("cvt.rna.tf32.f32 %0, %1;" : "=r"(u) : "f"(f));
    return u;
}

__device__ __forceinline__ void mma_tf32(float acc[4], unsigned a0, unsigned a1,
                                         unsigned a2, unsigned a3,
                                         unsigned b0, unsigned b1) {
    asm volatile(
        "mma.sync.aligned.m16n8k8.row.col.f32.tf32.tf32.f32 "
        "{%0,%1,%2,%3}, {%4,%5,%6,%7}, {%8,%9}, {%0,%1,%2,%3};"
        : "+f"(acc[0]), "+f"(acc[1]), "+f"(acc[2]), "+f"(acc[3])
        : "r"(a0), "r"(a1), "r"(a2), "r"(a3), "r"(b0), "r"(b1));
}

// Fused: blocks [0,GEMM_BLOCKS) compute y = x @ W^T (tf32 MMA, fp16 store);
//        blocks [GEMM_BLOCKS, +DEG_BLOCKS) build the in-degree histogram and
//        capture each edge's bucket rank (atomicAdd return value).
__global__ __launch_bounds__(256) void fused_gemm_deg_kernel(
        const float* __restrict__ W, const float* __restrict__ x,
        const int* __restrict__ col) {
    __shared__ unsigned sW[64 * 68];
    int tid = threadIdx.x;

    if (blockIdx.x >= GEMM_BLOCKS) {
        int e = (blockIdx.x - GEMM_BLOCKS) * 256 + tid;
        if (e < EE) g_rank[e] = atomicAdd(&g_degi[col[e]], 1);
        return;
    }

    #pragma unroll
    for (int t = tid; t < 4096; t += 256) {
        int n = t >> 6, k = t & 63;
        sW[n * 68 + k] = f2tf32(W[t]);
    }
    __syncthreads();

    int warp = tid >> 5, lane = tid & 31;
    int gid = lane >> 2, tg = lane & 3;
    int r0 = blockIdx.x * 128 + warp * 16;
    int rA = r0 + gid;
    int rB = rA + 8;
    int rAc = rA < NN ? rA : NN - 1;
    int rBc = rB < NN ? rB : NN - 1;
    const float* pA = x + rAc * 64 + tg;
    const float* pB = x + rBc * 64 + tg;

    float acc[8][4];
    #pragma unroll
    for (int n = 0; n < 8; n++)
        #pragma unroll
        for (int j = 0; j < 4; j++) acc[n][j] = 0.0f;

    #pragma unroll
    for (int s = 0; s < 8; s++) {
        int k0 = s * 8;
        unsigned a0 = f2tf32(pA[k0]);
        unsigned a1 = f2tf32(pB[k0]);
        unsigned a2 = f2tf32(pA[k0 + 4]);
        unsigned a3 = f2tf32(pB[k0 + 4]);
        #pragma unroll
        for (int n = 0; n < 8; n++) {
            unsigned b0 = sW[(n * 8 + gid) * 68 + k0 + tg];
            unsigned b1 = sW[(n * 8 + gid) * 68 + k0 + tg + 4];
            mma_tf32(acc[n], a0, a1, a2, a3, b0, b1);
        }
    }

    __half2* Yh2 = (__half2*)g_yh;     // half2 index = row*32 + col/2
    #pragma unroll
    for (int n = 0; n < 8; n++) {
        int cidx = n * 4 + tg;         // covers cols n*8+2tg, +1
        if (rA < NN) Yh2[rA * 32 + cidx] = __floats2half2_rn(acc[n][0], acc[n][1]);
        if (rB < NN) Yh2[rB * 32 + cidx] = __floats2half2_rn(acc[n][2], acc[n][3]);
    }
}

// ---------------------------------------------------------------------------
// Single-pass decoupled-lookback scan + finalize dinv/invdeg.
__global__ void scan_kernel() {
    __shared__ int wsum[32];
    __shared__ int sh_tile;
    __shared__ int sh_prefix;
    int tid = threadIdx.x, lane = tid & 31, wid = tid >> 5;

    if (tid == 0) sh_tile = atomicAdd(&g_ticket, 1);
    __syncthreads();
    int tile = sh_tile;
    int i = tile * 1024 + tid;
    int v = (i < NN) ? g_degi[i] : 0;

    int xs = v;
    #pragma unroll
    for (int d = 1; d < 32; d <<= 1) {
        int t = __shfl_up_sync(0xffffffffu, xs, d);
        if (lane >= d) xs += t;
    }
    if (lane == 31) wsum[wid] = xs;
    __syncthreads();
    if (wid == 0) {
        int s = wsum[lane];
        #pragma unroll
        for (int d = 1; d < 32; d <<= 1) {
            int t = __shfl_up_sync(0xffffffffu, s, d);
            if (lane >= d) s += t;
        }
        wsum[lane] = s;
    }
    __syncthreads();
    int incl = xs + (wid ? wsum[wid - 1] : 0);
    int total = wsum[31];

    if (tid == 0) {
        unsigned long long pack =
            ((unsigned long long)(tile == 0 ? 2u : 1u) << 32) | (unsigned)total;
        atomicExch(&g_state[tile], pack);
    }

    if (wid == 0) {
        int prefix = 0;
        if (tile > 0) {
            int base = tile - 1;
            while (true) {
                int t = base - lane;
                unsigned long long s;
                if (t >= 0) {
                    do { s = atomicAdd(&g_state[t], 0ULL); } while ((unsigned)(s >> 32) == 0u);
                } else {
                    s = (2ULL << 32);
                }
                unsigned flag = (unsigned)(s >> 32);
                int val = (int)(unsigned)s;
                unsigned ball = __ballot_sync(0xffffffffu, flag == 2u);
                int firstInc = __ffs(ball) - 1;
                int contrib = ball ? ((lane <= firstInc) ? val : 0) : val;
                #pragma unroll
                for (int d = 16; d; d >>= 1)
                    contrib += __shfl_xor_sync(0xffffffffu, contrib, d);
                prefix += contrib;
                if (ball) break;
                base -= 32;
            }
            if (lane == 0)
                atomicExch(&g_state[tile],
                           (2ULL << 32) | (unsigned)(prefix + total));
        }
        if (lane == 0) sh_prefix = prefix;
    }
    __syncthreads();
    int prefix = sh_prefix;
    if (i < NN) {
        g_start[i] = prefix + incl - v;
        float df = (float)v + 1.0f;
        g_dinv[i]   = rsqrtf(df);
        g_invdeg[i] = 1.0f / df;
    }
}

// ---------------------------------------------------------------------------
// bin: atomic-free CSR placement using precomputed ranks. 4 edges/thread.
__global__ __launch_bounds__(256) void bin_kernel(const int* __restrict__ row,
                                                  const int* __restrict__ col) {
    int base = (blockIdx.x * blockDim.x + threadIdx.x) * 4;
    #pragma unroll
    for (int u = 0; u < 4; u++) {
        int e = base + u;
        if (e < EE) {
            int c = col[e];
            g_csr[g_start[c] + g_rank[e]] = row[e];
        }
    }
}

// ---------------------------------------------------------------------------
// gather: out[c] = dinv[c] * sum_r dinv[r]*y[r] + y[c]/deg[c] + bias
// 16 threads per node; thread j owns fp16 columns 4j..4j+3 (one uint2).
__global__ void gather_kernel(const float* __restrict__ bias,
                              float4* __restrict__ out4) {
    int t = blockIdx.x * blockDim.x + threadIdx.x;
    int c = t >> 4;
    if (c >= NN) return;
    int j = t & 15;

    int start = g_start[c];
    int cnt   = g_degi[c];

    float4 acc = make_float4(0.f, 0.f, 0.f, 0.f);
    int k = 0;
    for (; k + 4 <= cnt; k += 4) {
        int r0 = g_csr[start + k];
        int r1 = g_csr[start + k + 1];
        int r2 = g_csr[start + k + 2];
        int r3 = g_csr[start + k + 3];
        float w0 = g_dinv[r0], w1 = g_dinv[r1], w2 = g_dinv[r2], w3 = g_dinv[r3];
        uint2 u0 = g_yh[r0 * 16 + j];
        uint2 u1 = g_yh[r1 * 16 + j];
        uint2 u2 = g_yh[r2 * 16 + j];
        uint2 u3 = g_yh[r3 * 16 + j];
        float2 a0 = __half22float2(*(__half2*)&u0.x), b0 = __half22float2(*(__half2*)&u0.y);
        float2 a1 = __half22float2(*(__half2*)&u1.x), b1 = __half22float2(*(__half2*)&u1.y);
        float2 a2 = __half22float2(*(__half2*)&u2.x), b2 = __half22float2(*(__half2*)&u2.y);
        float2 a3 = __half22float2(*(__half2*)&u3.x), b3 = __half22float2(*(__half2*)&u3.y);
        acc.x += w0 * a0.x + w1 * a1.x + w2 * a2.x + w3 * a3.x;
        acc.y += w0 * a0.y + w1 * a1.y + w2 * a2.y + w3 * a3.y;
        acc.z += w0 * b0.x + w1 * b1.x + w2 * b2.x + w3 * b3.x;
        acc.w += w0 * b0.y + w1 * b1.y + w2 * b2.y + w3 * b3.y;
    }
    for (; k < cnt; k++) {
        int r0 = g_csr[start + k];
        float w0 = g_dinv[r0];
        uint2 u0 = g_yh[r0 * 16 + j];
        float2 a0 = __half22float2(*(__half2*)&u0.x), b0 = __half22float2(*(__half2*)&u0.y);
        acc.x += w0 * a0.x;
        acc.y += w0 * a0.y;
        acc.z += w0 * b0.x;
        acc.w += w0 * b0.y;
    }

    float dc  = g_dinv[c];
    float inv = g_invdeg[c];
    uint2 us = g_yh[c * 16 + j];
    float2 s0 = __half22float2(*(__half2*)&us.x), s1 = __half22float2(*(__half2*)&us.y);
    float4 b4 = ((const float4*)bias)[j];

    float4 o;
    o.x = dc * acc.x + inv * s0.x + b4.x;
    o.y = dc * acc.y + inv * s0.y + b4.y;
    o.z = dc * acc.z + inv * s1.x + b4.z;
    o.w = dc * acc.w + inv * s1.y + b4.w;
    out4[c * 16 + j] = o;
}

// ---------------------------------------------------------------------------
extern "C" void kernel_launch(void* const* d_in, const int* in_sizes, int n_in,
                              void* d_out, int out_size) {
    const float* x  = nullptr;
    const int*   ei = nullptr;
    const float* Ww = nullptr;
    const float* Wb = nullptr;
    for (int i = 0; i < n_in; i++) {
        int sz = in_sizes[i];
        if (sz == 2 * EE)             ei = (const int*)d_in[i];
        else if (sz == DD * DD)       Ww = (const float*)d_in[i];
        else if (sz == DD)            Wb = (const float*)d_in[i];
        else if (sz == NN * DD && !x) x  = (const float*)d_in[i];
    }
    const int* row = ei;          // sources
    const int* col = ei + EE;     // targets
    float4* out4 = (float4*)d_out;

    clear_kernel         <<<(NN + 255) / 256, 256>>>();
    fused_gemm_deg_kernel<<<GEMM_BLOCKS + DEG_BLOCKS, 256>>>(Ww, x, col);
    scan_kernel          <<<NB, 1024>>>();
    bin_kernel           <<<(EE / 4 + 255) / 256, 256>>>(row, col);
    gather_kernel        <<<(NN * 16 + 255) / 256, 256>>>(Wb, out4);
}